// round 1
// baseline (speedup 1.0000x reference)
#include <cuda_runtime.h>
#include <math.h>

// Problem constants
#define MROWS 4096   // B*T
#define CEMB  2048
#define TSEQ  2048
#define NHEAD 16
#define NGROUP 4
#define DHEAD 128
#define KVC   512    // NGROUP*DHEAD
#define SWIN  512
#define SINK  4

// Scratch (static device globals: allocation-free rule)
__device__ float g_Q[(size_t)MROWS * CEMB];
__device__ float g_K[(size_t)MROWS * KVC];
__device__ float g_V[(size_t)MROWS * KVC];
__device__ float g_O[(size_t)MROWS * CEMB];

// ---------------------------------------------------------------------------
// SGEMM: C[M,N] = A[M,K] @ B[K,N] + bias[N]
// BM=128, BN=128, BK=8, 256 threads, 8x8 per thread.
// Assumes M%128==0, N%128==0, K%8==0 (true for all four calls).
// ---------------------------------------------------------------------------
__global__ __launch_bounds__(256) void sgemm_bias(
    int M, int N, int K,
    const float* __restrict__ A, const float* __restrict__ B,
    const float* __restrict__ bias, float* __restrict__ C)
{
    constexpr int BM = 128, BN = 128, BK = 8, TM = 8, TN = 8;
    __shared__ float As[BK][BM];
    __shared__ float Bs[BK][BN];

    const int tid  = threadIdx.x;
    const int trow = tid >> 4;      // 0..15
    const int tcol = tid & 15;      // 0..15

    float acc[TM][TN];
#pragma unroll
    for (int i = 0; i < TM; i++)
#pragma unroll
        for (int j = 0; j < TN; j++) acc[i][j] = 0.f;

    const float* Ab = A + (size_t)blockIdx.y * BM * K;
    const float* Bb = B + (size_t)blockIdx.x * BN;

    const int aRow = tid >> 1;          // 0..127
    const int aCol = (tid & 1) * 4;     // 0 or 4
    const int bRow = tid >> 5;          // 0..7
    const int bCol = (tid & 31) * 4;    // 0..124

    for (int k0 = 0; k0 < K; k0 += BK) {
        float4 a = *(const float4*)(Ab + (size_t)aRow * K + k0 + aCol);
        As[aCol + 0][aRow] = a.x;
        As[aCol + 1][aRow] = a.y;
        As[aCol + 2][aRow] = a.z;
        As[aCol + 3][aRow] = a.w;
        *(float4*)(&Bs[bRow][bCol]) =
            *(const float4*)(Bb + (size_t)(k0 + bRow) * N + bCol);
        __syncthreads();

#pragma unroll
        for (int k = 0; k < BK; k++) {
            float4 a0 = *(const float4*)(&As[k][trow * TM]);
            float4 a1 = *(const float4*)(&As[k][trow * TM + 4]);
            float4 b0 = *(const float4*)(&Bs[k][tcol * TN]);
            float4 b1 = *(const float4*)(&Bs[k][tcol * TN + 4]);
            float ra[8] = {a0.x, a0.y, a0.z, a0.w, a1.x, a1.y, a1.z, a1.w};
            float rb[8] = {b0.x, b0.y, b0.z, b0.w, b1.x, b1.y, b1.z, b1.w};
#pragma unroll
            for (int i = 0; i < TM; i++)
#pragma unroll
                for (int j = 0; j < TN; j++)
                    acc[i][j] += ra[i] * rb[j];
        }
        __syncthreads();
    }

#pragma unroll
    for (int i = 0; i < TM; i++) {
        int row = blockIdx.y * BM + trow * TM + i;
#pragma unroll
        for (int j = 0; j < TN; j += 4) {
            int col = blockIdx.x * BN + tcol * TN + j;
            float4 o;
            o.x = acc[i][j + 0] + bias[col + 0];
            o.y = acc[i][j + 1] + bias[col + 1];
            o.z = acc[i][j + 2] + bias[col + 2];
            o.w = acc[i][j + 3] + bias[col + 3];
            *(float4*)(C + (size_t)row * N + col) = o;
        }
    }
}

// ---------------------------------------------------------------------------
// RoPE (half-rotation / concat style), POS = 0.
// X: [MROWS, nheads*128]; token index t = row % TSEQ.
// Uses accurate sincosf (t*inv_freq up to ~2047 rad needs real range reduction)
// ---------------------------------------------------------------------------
__global__ void rope_kernel(float* __restrict__ X, int nheads)
{
    int idx = blockIdx.x * blockDim.x + threadIdx.x;
    int total = MROWS * nheads * 64;
    if (idx >= total) return;
    int d = idx & 63;
    int h = (idx >> 6) % nheads;
    int r = idx / (64 * nheads);
    int t = r & (TSEQ - 1);

    float inv = powf(10000.f, -(float)d * (1.f / 64.f));
    float ang = (float)t * inv;
    float s, c;
    sincosf(ang, &s, &c);

    int Cw = nheads * DHEAD;
    float* p = X + (size_t)r * Cw + h * DHEAD + d;
    float x1 = p[0], x2 = p[64];
    p[0]  = x1 * c - x2 * s;
    p[64] = x1 * s + x2 * c;
}

// ---------------------------------------------------------------------------
// Attention: grid (q_tiles=32, b*h=32). CTA = 256 threads = 8 warps.
// Each warp owns 8 query rows (online softmax state in registers; each lane
// holds 4 of the 128 head dims). KV staged in 32-row shared tiles.
// ---------------------------------------------------------------------------
__global__ __launch_bounds__(256) void attn_kernel()
{
    constexpr int QT = 64, KT = 32;
    __shared__ float4 Ks[KT * 32];   // [j][d4]
    __shared__ float4 Vs[KT * 32];

    const int qtile = blockIdx.x;
    const int bh    = blockIdx.y;
    const int b = bh >> 4, h = bh & 15, g = h >> 2;
    const int warp = threadIdx.x >> 5, lane = threadIdx.x & 31;
    const int qs = qtile * QT;

    float4 qv[8], acc[8];
    float  mx[8], l[8];
#pragma unroll
    for (int k = 0; k < 8; k++) {
        int i = qs + warp * 8 + k;
        qv[k] = *(const float4*)(g_Q + (size_t)(b * TSEQ + i) * CEMB
                                 + h * DHEAD + lane * 4);
        acc[k] = make_float4(0.f, 0.f, 0.f, 0.f);
        mx[k] = -1e30f;
        l[k] = 0.f;
    }
    const float scale = 0.08838834764831845f; // 1/sqrt(128)
    const int qe = qs + QT;

    for (int ts = 0; ts < qe; ts += KT) {
        // tile needed iff it holds sinks or overlaps [qs-SWIN, qe)
        if (!(ts == 0 || ts + KT - 1 >= qs - SWIN)) continue;

        // cooperative load of K/V tile: KT*32 float4 = 1024, 4 per thread
#pragma unroll
        for (int r2 = 0; r2 < (KT * 32) / 256; r2++) {
            int idx = threadIdx.x + r2 * 256;
            int j = idx >> 5, d4 = idx & 31;
            size_t goff = (size_t)(b * TSEQ + ts + j) * KVC + g * DHEAD + d4 * 4;
            Ks[idx] = *(const float4*)(g_K + goff);
            Vs[idx] = *(const float4*)(g_V + goff);
        }
        __syncthreads();

        for (int j = 0; j < KT; j++) {
            int jg = ts + j;
            float4 kf = Ks[j * 32 + lane];
            float4 vf = Vs[j * 32 + lane];
#pragma unroll
            for (int k = 0; k < 8; k++) {
                int i = qs + warp * 8 + k;
                if (jg > i || (jg < i - SWIN && jg >= SINK)) continue;
                float s = qv[k].x * kf.x + qv[k].y * kf.y
                        + qv[k].z * kf.z + qv[k].w * kf.w;
                s += __shfl_xor_sync(0xffffffffu, s, 16);
                s += __shfl_xor_sync(0xffffffffu, s, 8);
                s += __shfl_xor_sync(0xffffffffu, s, 4);
                s += __shfl_xor_sync(0xffffffffu, s, 2);
                s += __shfl_xor_sync(0xffffffffu, s, 1);
                s *= scale;
                float mn   = fmaxf(mx[k], s);
                float p    = __expf(s - mn);
                float corr = __expf(mx[k] - mn);
                l[k] = l[k] * corr + p;
                acc[k].x = acc[k].x * corr + p * vf.x;
                acc[k].y = acc[k].y * corr + p * vf.y;
                acc[k].z = acc[k].z * corr + p * vf.z;
                acc[k].w = acc[k].w * corr + p * vf.w;
                mx[k] = mn;
            }
        }
        __syncthreads();
    }

#pragma unroll
    for (int k = 0; k < 8; k++) {
        int i = qs + warp * 8 + k;
        float inv_l = 1.f / l[k];
        float4 o = make_float4(acc[k].x * inv_l, acc[k].y * inv_l,
                               acc[k].z * inv_l, acc[k].w * inv_l);
        *(float4*)(g_O + (size_t)(b * TSEQ + i) * CEMB + h * DHEAD + lane * 4) = o;
    }
}

// ---------------------------------------------------------------------------
extern "C" void kernel_launch(void* const* d_in, const int* in_sizes, int n_in,
                              void* d_out, int out_size)
{
    const float* x  = (const float*)d_in[0];
    const float* Wq = (const float*)d_in[1];
    const float* bq = (const float*)d_in[2];
    const float* Wk = (const float*)d_in[3];
    const float* bk = (const float*)d_in[4];
    const float* Wv = (const float*)d_in[5];
    const float* bv = (const float*)d_in[6];
    const float* Wo = (const float*)d_in[7];
    const float* bo = (const float*)d_in[8];
    float* out = (float*)d_out;

    float *Q, *K, *V, *O;
    cudaGetSymbolAddress((void**)&Q, g_Q);
    cudaGetSymbolAddress((void**)&K, g_K);
    cudaGetSymbolAddress((void**)&V, g_V);
    cudaGetSymbolAddress((void**)&O, g_O);

    // QKV projections
    sgemm_bias<<<dim3(CEMB / 128, MROWS / 128), 256>>>(MROWS, CEMB, CEMB, x, Wq, bq, Q);
    sgemm_bias<<<dim3(KVC  / 128, MROWS / 128), 256>>>(MROWS, KVC,  CEMB, x, Wk, bk, K);
    sgemm_bias<<<dim3(KVC  / 128, MROWS / 128), 256>>>(MROWS, KVC,  CEMB, x, Wv, bv, V);

    // RoPE on Q and K
    rope_kernel<<<(MROWS * NHEAD * 64) / 256, 256>>>(Q, NHEAD);
    rope_kernel<<<(MROWS * NGROUP * 64) / 256, 256>>>(K, NGROUP);

    // Attention (sliding window + sink, online softmax)
    attn_kernel<<<dim3(TSEQ / 64, 2 * NHEAD), 256>>>();

    // Output projection
    sgemm_bias<<<dim3(CEMB / 128, MROWS / 128), 256>>>(MROWS, CEMB, CEMB, O, Wo, bo, out);
}

// round 3
// speedup vs baseline: 1.4547x; 1.4547x over previous
#include <cuda_runtime.h>
#include <cuda_bf16.h>
#include <math.h>
#include <stdint.h>

// Problem constants
#define MROWS 4096   // B*T
#define CEMB  2048
#define TSEQ  2048
#define NHEAD 16
#define NGROUP 4
#define DHEAD 128
#define KVC   512
#define SWIN  512
#define SINK  4

// fp32 scratch
__device__ float g_Q[(size_t)MROWS * CEMB];
__device__ float g_K[(size_t)MROWS * KVC];
__device__ float g_V[(size_t)MROWS * KVC];
__device__ float g_O[(size_t)MROWS * CEMB];

// bf16 split scratch
__device__ __nv_bfloat16 g_xhi[(size_t)MROWS * CEMB];
__device__ __nv_bfloat16 g_xlo[(size_t)MROWS * CEMB];
__device__ __nv_bfloat16 g_ohi[(size_t)MROWS * CEMB];
__device__ __nv_bfloat16 g_olo[(size_t)MROWS * CEMB];
__device__ __nv_bfloat16 g_WqT_hi[(size_t)CEMB * CEMB];
__device__ __nv_bfloat16 g_WqT_lo[(size_t)CEMB * CEMB];
__device__ __nv_bfloat16 g_WkT_hi[(size_t)KVC * CEMB];
__device__ __nv_bfloat16 g_WkT_lo[(size_t)KVC * CEMB];
__device__ __nv_bfloat16 g_WvT_hi[(size_t)KVC * CEMB];
__device__ __nv_bfloat16 g_WvT_lo[(size_t)KVC * CEMB];
__device__ __nv_bfloat16 g_WoT_hi[(size_t)CEMB * CEMB];
__device__ __nv_bfloat16 g_WoT_lo[(size_t)CEMB * CEMB];

// ---------------------------------------------------------------------------
// helpers
// ---------------------------------------------------------------------------
__device__ __forceinline__ uint32_t cvta_s(const void* p) {
    return (uint32_t)__cvta_generic_to_shared(p);
}
__device__ __forceinline__ void cp16(uint32_t dst, const void* src) {
    asm volatile("cp.async.cg.shared.global [%0], [%1], 16;\n" :: "r"(dst), "l"(src));
}
#define CP_COMMIT() asm volatile("cp.async.commit_group;\n" ::: "memory")
#define CP_WAIT(n)  asm volatile("cp.async.wait_group %0;\n" :: "n"(n) : "memory")

#define LDSM4(r, addr) \
    asm volatile("ldmatrix.sync.aligned.m8n8.x4.shared.b16 {%0,%1,%2,%3}, [%4];" \
        : "=r"((r)[0]), "=r"((r)[1]), "=r"((r)[2]), "=r"((r)[3]) : "r"(addr))

#define MMA16816(c, a, b0, b1) \
    asm volatile("mma.sync.aligned.m16n8k16.row.col.f32.bf16.bf16.f32 " \
        "{%0,%1,%2,%3},{%4,%5,%6,%7},{%8,%9},{%0,%1,%2,%3};" \
        : "+f"((c)[0]), "+f"((c)[1]), "+f"((c)[2]), "+f"((c)[3]) \
        : "r"((a)[0]), "r"((a)[1]), "r"((a)[2]), "r"((a)[3]), "r"(b0), "r"(b1))

// ---------------------------------------------------------------------------
// split fp32 -> bf16 hi/lo (vectorized by 4)
// ---------------------------------------------------------------------------
__global__ void split_f32(const float* __restrict__ s,
                          __nv_bfloat16* __restrict__ hi,
                          __nv_bfloat16* __restrict__ lo, int n4)
{
    int i = blockIdx.x * blockDim.x + threadIdx.x;
    if (i >= n4) return;
    float4 v = ((const float4*)s)[i];
    __nv_bfloat16 h0 = __float2bfloat16_rn(v.x);
    __nv_bfloat16 h1 = __float2bfloat16_rn(v.y);
    __nv_bfloat16 h2 = __float2bfloat16_rn(v.z);
    __nv_bfloat16 h3 = __float2bfloat16_rn(v.w);
    __nv_bfloat16 l0 = __float2bfloat16_rn(v.x - __bfloat162float(h0));
    __nv_bfloat16 l1 = __float2bfloat16_rn(v.y - __bfloat162float(h1));
    __nv_bfloat16 l2 = __float2bfloat16_rn(v.z - __bfloat162float(h2));
    __nv_bfloat16 l3 = __float2bfloat16_rn(v.w - __bfloat162float(h3));
    __nv_bfloat162* ph = (__nv_bfloat162*)hi;
    __nv_bfloat162* pl = (__nv_bfloat162*)lo;
    ph[i * 2 + 0] = __nv_bfloat162(h0, h1);
    ph[i * 2 + 1] = __nv_bfloat162(h2, h3);
    pl[i * 2 + 0] = __nv_bfloat162(l0, l1);
    pl[i * 2 + 1] = __nv_bfloat162(l2, l3);
}

// ---------------------------------------------------------------------------
// transpose + split: W[K][N] fp32 -> WT[N][K] bf16 hi/lo
// ---------------------------------------------------------------------------
__global__ void tsplit(const float* __restrict__ W,
                       __nv_bfloat16* __restrict__ hi,
                       __nv_bfloat16* __restrict__ lo, int K, int N)
{
    __shared__ float t[32][33];
    int n0 = blockIdx.x * 32, k0 = blockIdx.y * 32;
    int tx = threadIdx.x, ty = threadIdx.y;
#pragma unroll
    for (int i = 0; i < 4; i++)
        t[ty + 8 * i][tx] = W[(size_t)(k0 + ty + 8 * i) * N + n0 + tx];
    __syncthreads();
#pragma unroll
    for (int i = 0; i < 4; i++) {
        float v = t[tx][ty + 8 * i];
        __nv_bfloat16 h = __float2bfloat16_rn(v);
        size_t off = (size_t)(n0 + ty + 8 * i) * K + k0 + tx;
        hi[off] = h;
        lo[off] = __float2bfloat16_rn(v - __bfloat162float(h));
    }
}

// ---------------------------------------------------------------------------
// HMMA GEMM: C[M,N] = Ahi@Bhi^T + Ahi@Blo^T + Alo@Bhi^T + bias
// A*: [M,2048] bf16 row-major, B*: [N,2048] bf16 row-major.
// CTA 128x128, BK=64 (128B rows, SW128 xor swizzle), 2-stage cp.async.
// 256 threads = 8 warps in 2(m) x 4(n); warp tile 64x32.
// ---------------------------------------------------------------------------
__global__ __launch_bounds__(256, 1) void gemm_mma(
    int M, int N,
    const __nv_bfloat16* __restrict__ Ahi, const __nv_bfloat16* __restrict__ Alo,
    const __nv_bfloat16* __restrict__ Bhi, const __nv_bfloat16* __restrict__ Blo,
    const float* __restrict__ bias, float* __restrict__ C)
{
    constexpr int KD = 2048;
    constexpr int NCHUNK = KD / 64;  // 32
    extern __shared__ char dsm[];
    uint32_t sbase = (cvta_s(dsm) + 1023) & ~1023u;

    const int tid = threadIdx.x;
    const int wid = tid >> 5, lane = tid & 31;
    const int wm = wid >> 2, wn = wid & 3;     // 2 x 4 warp grid
    const int m0 = blockIdx.y * 128, n0 = blockIdx.x * 128;

    // cp.async slots: 4 per buffer; row = idx/8, 16B chunk = idx%8
    uint32_t dsts[4];
    size_t gA[4], gB[4];
#pragma unroll
    for (int p = 0; p < 4; p++) {
        int idx = tid + p * 256;
        int row = idx >> 3, ch = idx & 7;
        dsts[p] = row * 128 + ((ch ^ (row & 7)) * 16);
        gA[p] = (size_t)(m0 + row) * KD + ch * 8;
        gB[p] = (size_t)(n0 + row) * KD + ch * 8;
    }

    // ldmatrix per-thread row bases
    // A (16x16, x4): lanes 0-7 rows+0..7, 8-15 rows+8..15 (k lo 16B); 16-31 same rows (k hi 16B)
    const int arow = (lane & 7) + ((lane >> 3) & 1) * 8;   // row within 16
    const int acb  = lane >> 4;                            // chunk bit
    // B (16 n-rows x 16k, x4): lanes 0-7 n+0..7 klo, 8-15 n+0..7 khi, 16-23 n+8..15 klo, 24-31 khi
    const int brow = (lane & 7) + (lane >> 4) * 8;
    const int bcb  = (lane >> 3) & 1;

    float acc[4][4][4];
#pragma unroll
    for (int i = 0; i < 4; i++)
#pragma unroll
        for (int j = 0; j < 4; j++) {
            acc[i][j][0] = 0.f; acc[i][j][1] = 0.f;
            acc[i][j][2] = 0.f; acc[i][j][3] = 0.f;
        }

    // prefetch chunk 0
#pragma unroll
    for (int p = 0; p < 4; p++) {
        uint32_t st = sbase;
        cp16(st +     0 + dsts[p], Ahi + gA[p]);
        cp16(st + 16384 + dsts[p], Alo + gA[p]);
        cp16(st + 32768 + dsts[p], Bhi + gB[p]);
        cp16(st + 49152 + dsts[p], Blo + gB[p]);
    }
    CP_COMMIT();

    for (int c = 0; c < NCHUNK; c++) {
        if (c + 1 < NCHUNK) {
            uint32_t st = sbase + ((c + 1) & 1) * 65536;
            int k0 = (c + 1) * 64;
#pragma unroll
            for (int p = 0; p < 4; p++) {
                cp16(st +     0 + dsts[p], Ahi + gA[p] + k0);
                cp16(st + 16384 + dsts[p], Alo + gA[p] + k0);
                cp16(st + 32768 + dsts[p], Bhi + gB[p] + k0);
                cp16(st + 49152 + dsts[p], Blo + gB[p] + k0);
            }
            CP_COMMIT();
            CP_WAIT(1);
        } else {
            CP_WAIT(0);
        }
        __syncthreads();

        uint32_t st = sbase + (c & 1) * 65536;
        uint32_t aHiB = st +     0;
        uint32_t aLoB = st + 16384;
        uint32_t bHiB = st + 32768;
        uint32_t bLoB = st + 49152;

#pragma unroll
        for (int ks = 0; ks < 4; ks++) {
            uint32_t ahi[4][4], alo[4][4], bhi[2][4], blo[2][4];
            // A rows
#pragma unroll
            for (int mt = 0; mt < 4; mt++) {
                int r = wm * 64 + mt * 16 + arow;
                uint32_t off = r * 128 + (((2 * ks + acb) ^ (r & 7)) * 16);
                LDSM4(ahi[mt], aHiB + off);
            }
            // B hi
#pragma unroll
            for (int np = 0; np < 2; np++) {
                int r = wn * 32 + np * 16 + brow;
                uint32_t off = r * 128 + (((2 * ks + bcb) ^ (r & 7)) * 16);
                LDSM4(bhi[np], bHiB + off);
            }
#pragma unroll
            for (int mt = 0; mt < 4; mt++)
#pragma unroll
                for (int nt = 0; nt < 4; nt++)
                    MMA16816(acc[mt][nt], ahi[mt], bhi[nt >> 1][(nt & 1) * 2],
                             bhi[nt >> 1][(nt & 1) * 2 + 1]);
            // B lo
#pragma unroll
            for (int np = 0; np < 2; np++) {
                int r = wn * 32 + np * 16 + brow;
                uint32_t off = r * 128 + (((2 * ks + bcb) ^ (r & 7)) * 16);
                LDSM4(blo[np], bLoB + off);
            }
#pragma unroll
            for (int mt = 0; mt < 4; mt++)
#pragma unroll
                for (int nt = 0; nt < 4; nt++)
                    MMA16816(acc[mt][nt], ahi[mt], blo[nt >> 1][(nt & 1) * 2],
                             blo[nt >> 1][(nt & 1) * 2 + 1]);
            // A lo x B hi
#pragma unroll
            for (int mt = 0; mt < 4; mt++) {
                int r = wm * 64 + mt * 16 + arow;
                uint32_t off = r * 128 + (((2 * ks + acb) ^ (r & 7)) * 16);
                LDSM4(alo[mt], aLoB + off);
            }
#pragma unroll
            for (int mt = 0; mt < 4; mt++)
#pragma unroll
                for (int nt = 0; nt < 4; nt++)
                    MMA16816(acc[mt][nt], alo[mt], bhi[nt >> 1][(nt & 1) * 2],
                             bhi[nt >> 1][(nt & 1) * 2 + 1]);
        }
        __syncthreads();
    }

    // epilogue
#pragma unroll
    for (int mt = 0; mt < 4; mt++) {
        int r0 = m0 + wm * 64 + mt * 16 + (lane >> 2);
#pragma unroll
        for (int nt = 0; nt < 4; nt++) {
            int cc = n0 + wn * 32 + nt * 8 + (lane & 3) * 2;
            float b0 = bias[cc], b1 = bias[cc + 1];
            float2 v0 = make_float2(acc[mt][nt][0] + b0, acc[mt][nt][1] + b1);
            float2 v1 = make_float2(acc[mt][nt][2] + b0, acc[mt][nt][3] + b1);
            *(float2*)(C + (size_t)r0 * N + cc) = v0;
            *(float2*)(C + (size_t)(r0 + 8) * N + cc) = v1;
        }
    }
}

// ---------------------------------------------------------------------------
// RoPE (accurate sincosf), POS = 0
// ---------------------------------------------------------------------------
__global__ void rope_kernel(float* __restrict__ X, int nheads)
{
    int idx = blockIdx.x * blockDim.x + threadIdx.x;
    int total = MROWS * nheads * 64;
    if (idx >= total) return;
    int d = idx & 63;
    int h = (idx >> 6) % nheads;
    int r = idx / (64 * nheads);
    int t = r & (TSEQ - 1);

    float inv = powf(10000.f, -(float)d * (1.f / 64.f));
    float ang = (float)t * inv;
    float s, c;
    sincosf(ang, &s, &c);

    int Cw = nheads * DHEAD;
    float* p = X + (size_t)r * Cw + h * DHEAD + d;
    float x1 = p[0], x2 = p[64];
    p[0]  = x1 * c - x2 * s;
    p[64] = x1 * s + x2 * c;
}

// ---------------------------------------------------------------------------
// Attention (sliding window + sink, online softmax)
// ---------------------------------------------------------------------------
__global__ __launch_bounds__(256) void attn_kernel()
{
    constexpr int QT = 64, KT = 32;
    __shared__ float4 Ks[KT * 32];
    __shared__ float4 Vs[KT * 32];

    const int qtile = blockIdx.x;
    const int bh    = blockIdx.y;
    const int b = bh >> 4, h = bh & 15, g = h >> 2;
    const int warp = threadIdx.x >> 5, lane = threadIdx.x & 31;
    const int qs = qtile * QT;

    float4 qv[8], acc[8];
    float  mx[8], l[8];
#pragma unroll
    for (int k = 0; k < 8; k++) {
        int i = qs + warp * 8 + k;
        qv[k] = *(const float4*)(g_Q + (size_t)(b * TSEQ + i) * CEMB
                                 + h * DHEAD + lane * 4);
        acc[k] = make_float4(0.f, 0.f, 0.f, 0.f);
        mx[k] = -1e30f;
        l[k] = 0.f;
    }
    const float scale = 0.08838834764831845f;
    const int qe = qs + QT;

    for (int ts = 0; ts < qe; ts += KT) {
        if (!(ts == 0 || ts + KT - 1 >= qs - SWIN)) continue;

#pragma unroll
        for (int r2 = 0; r2 < (KT * 32) / 256; r2++) {
            int idx = threadIdx.x + r2 * 256;
            int j = idx >> 5, d4 = idx & 31;
            size_t goff = (size_t)(b * TSEQ + ts + j) * KVC + g * DHEAD + d4 * 4;
            Ks[idx] = *(const float4*)(g_K + goff);
            Vs[idx] = *(const float4*)(g_V + goff);
        }
        __syncthreads();

        for (int j = 0; j < KT; j++) {
            int jg = ts + j;
            float4 kf = Ks[j * 32 + lane];
            float4 vf = Vs[j * 32 + lane];
#pragma unroll
            for (int k = 0; k < 8; k++) {
                int i = qs + warp * 8 + k;
                if (jg > i || (jg < i - SWIN && jg >= SINK)) continue;
                float s = qv[k].x * kf.x + qv[k].y * kf.y
                        + qv[k].z * kf.z + qv[k].w * kf.w;
                s += __shfl_xor_sync(0xffffffffu, s, 16);
                s += __shfl_xor_sync(0xffffffffu, s, 8);
                s += __shfl_xor_sync(0xffffffffu, s, 4);
                s += __shfl_xor_sync(0xffffffffu, s, 2);
                s += __shfl_xor_sync(0xffffffffu, s, 1);
                s *= scale;
                float mn   = fmaxf(mx[k], s);
                float p    = __expf(s - mn);
                float corr = __expf(mx[k] - mn);
                l[k] = l[k] * corr + p;
                acc[k].x = acc[k].x * corr + p * vf.x;
                acc[k].y = acc[k].y * corr + p * vf.y;
                acc[k].z = acc[k].z * corr + p * vf.z;
                acc[k].w = acc[k].w * corr + p * vf.w;
                mx[k] = mn;
            }
        }
        __syncthreads();
    }

#pragma unroll
    for (int k = 0; k < 8; k++) {
        int i = qs + warp * 8 + k;
        float inv_l = 1.f / l[k];
        float4 o = make_float4(acc[k].x * inv_l, acc[k].y * inv_l,
                               acc[k].z * inv_l, acc[k].w * inv_l);
        *(float4*)(g_O + (size_t)(b * TSEQ + i) * CEMB + h * DHEAD + lane * 4) = o;
    }
}

// ---------------------------------------------------------------------------
extern "C" void kernel_launch(void* const* d_in, const int* in_sizes, int n_in,
                              void* d_out, int out_size)
{
    const float* x  = (const float*)d_in[0];
    const float* Wq = (const float*)d_in[1];
    const float* bq = (const float*)d_in[2];
    const float* Wk = (const float*)d_in[3];
    const float* bk = (const float*)d_in[4];
    const float* Wv = (const float*)d_in[5];
    const float* bv = (const float*)d_in[6];
    const float* Wo = (const float*)d_in[7];
    const float* bo = (const float*)d_in[8];
    float* out = (float*)d_out;

    float *Q, *K, *V, *O;
    cudaGetSymbolAddress((void**)&Q, g_Q);
    cudaGetSymbolAddress((void**)&K, g_K);
    cudaGetSymbolAddress((void**)&V, g_V);
    cudaGetSymbolAddress((void**)&O, g_O);
    __nv_bfloat16 *xhi, *xlo, *ohi, *olo;
    __nv_bfloat16 *wqh, *wql, *wkh, *wkl, *wvh, *wvl, *woh, *wol;
    cudaGetSymbolAddress((void**)&xhi, g_xhi);
    cudaGetSymbolAddress((void**)&xlo, g_xlo);
    cudaGetSymbolAddress((void**)&ohi, g_ohi);
    cudaGetSymbolAddress((void**)&olo, g_olo);
    cudaGetSymbolAddress((void**)&wqh, g_WqT_hi);
    cudaGetSymbolAddress((void**)&wql, g_WqT_lo);
    cudaGetSymbolAddress((void**)&wkh, g_WkT_hi);
    cudaGetSymbolAddress((void**)&wkl, g_WkT_lo);
    cudaGetSymbolAddress((void**)&wvh, g_WvT_hi);
    cudaGetSymbolAddress((void**)&wvl, g_WvT_lo);
    cudaGetSymbolAddress((void**)&woh, g_WoT_hi);
    cudaGetSymbolAddress((void**)&wol, g_WoT_lo);

    const int GEMM_SMEM = 132096;  // 2 stages * 64KB + align slack
    cudaFuncSetAttribute(gemm_mma, cudaFuncAttributeMaxDynamicSharedMemorySize, GEMM_SMEM);

    // splits / transposes
    {
        int n4 = (MROWS * CEMB) / 4;
        split_f32<<<(n4 + 255) / 256, 256>>>(x, xhi, xlo, n4);
    }
    tsplit<<<dim3(CEMB / 32, CEMB / 32), dim3(32, 8)>>>(Wq, wqh, wql, CEMB, CEMB);
    tsplit<<<dim3(KVC  / 32, CEMB / 32), dim3(32, 8)>>>(Wk, wkh, wkl, CEMB, KVC);
    tsplit<<<dim3(KVC  / 32, CEMB / 32), dim3(32, 8)>>>(Wv, wvh, wvl, CEMB, KVC);
    tsplit<<<dim3(CEMB / 32, CEMB / 32), dim3(32, 8)>>>(Wo, woh, wol, CEMB, CEMB);

    // projections on tensor cores (legacy HMMA path)
    gemm_mma<<<dim3(CEMB / 128, MROWS / 128), 256, GEMM_SMEM>>>(
        MROWS, CEMB, xhi, xlo, wqh, wql, bq, Q);
    gemm_mma<<<dim3(KVC / 128, MROWS / 128), 256, GEMM_SMEM>>>(
        MROWS, KVC, xhi, xlo, wkh, wkl, bk, K);
    gemm_mma<<<dim3(KVC / 128, MROWS / 128), 256, GEMM_SMEM>>>(
        MROWS, KVC, xhi, xlo, wvh, wvl, bv, V);

    // RoPE
    rope_kernel<<<(MROWS * NHEAD * 64) / 256, 256>>>(Q, NHEAD);
    rope_kernel<<<(MROWS * NGROUP * 64) / 256, 256>>>(K, NGROUP);

    // attention
    attn_kernel<<<dim3(TSEQ / 64, 2 * NHEAD), 256>>>();

    // output projection
    {
        int n4 = (MROWS * CEMB) / 4;
        split_f32<<<(n4 + 255) / 256, 256>>>(O, ohi, olo, n4);
    }
    gemm_mma<<<dim3(CEMB / 128, MROWS / 128), 256, GEMM_SMEM>>>(
        MROWS, CEMB, ohi, olo, woh, wol, bo, out);
}

// round 4
// speedup vs baseline: 4.9519x; 3.4041x over previous
#include <cuda_runtime.h>
#include <cuda_bf16.h>
#include <math.h>
#include <stdint.h>

// Problem constants
#define MROWS 4096   // B*T
#define CEMB  2048
#define TSEQ  2048
#define NHEAD 16
#define NGROUP 4
#define DHEAD 128
#define KVC   512
#define SWIN  512
#define SINK  4

// fp32 scratch
__device__ float g_Q[(size_t)MROWS * CEMB];
__device__ float g_K[(size_t)MROWS * KVC];
__device__ float g_V[(size_t)MROWS * KVC];

// bf16 split scratch
__device__ __nv_bfloat16 g_xhi[(size_t)MROWS * CEMB];
__device__ __nv_bfloat16 g_xlo[(size_t)MROWS * CEMB];
__device__ __nv_bfloat16 g_ohi[(size_t)MROWS * CEMB];
__device__ __nv_bfloat16 g_olo[(size_t)MROWS * CEMB];
__device__ __nv_bfloat16 g_qhi[(size_t)MROWS * CEMB];   // [b,h,t,d]
__device__ __nv_bfloat16 g_qlo[(size_t)MROWS * CEMB];
__device__ __nv_bfloat16 g_khi[(size_t)MROWS * KVC];    // [b,g,t,d]
__device__ __nv_bfloat16 g_klo[(size_t)MROWS * KVC];
__device__ __nv_bfloat16 g_vhi[(size_t)MROWS * KVC];
__device__ __nv_bfloat16 g_vlo[(size_t)MROWS * KVC];
__device__ __nv_bfloat16 g_WqT_hi[(size_t)CEMB * CEMB];
__device__ __nv_bfloat16 g_WqT_lo[(size_t)CEMB * CEMB];
__device__ __nv_bfloat16 g_WkT_hi[(size_t)KVC * CEMB];
__device__ __nv_bfloat16 g_WkT_lo[(size_t)KVC * CEMB];
__device__ __nv_bfloat16 g_WvT_hi[(size_t)KVC * CEMB];
__device__ __nv_bfloat16 g_WvT_lo[(size_t)KVC * CEMB];
__device__ __nv_bfloat16 g_WoT_hi[(size_t)CEMB * CEMB];
__device__ __nv_bfloat16 g_WoT_lo[(size_t)CEMB * CEMB];

// ---------------------------------------------------------------------------
// helpers
// ---------------------------------------------------------------------------
__device__ __forceinline__ uint32_t cvta_s(const void* p) {
    return (uint32_t)__cvta_generic_to_shared(p);
}
__device__ __forceinline__ void cp16(uint32_t dst, const void* src) {
    asm volatile("cp.async.cg.shared.global [%0], [%1], 16;\n" :: "r"(dst), "l"(src));
}
#define CP_COMMIT() asm volatile("cp.async.commit_group;\n" ::: "memory")
#define CP_WAIT(n)  asm volatile("cp.async.wait_group %0;\n" :: "n"(n) : "memory")

#define LDSM4(r, addr) \
    asm volatile("ldmatrix.sync.aligned.m8n8.x4.shared.b16 {%0,%1,%2,%3}, [%4];" \
        : "=r"((r)[0]), "=r"((r)[1]), "=r"((r)[2]), "=r"((r)[3]) : "r"(addr))

#define LDSM4T(r, addr) \
    asm volatile("ldmatrix.sync.aligned.m8n8.x4.trans.shared.b16 {%0,%1,%2,%3}, [%4];" \
        : "=r"((r)[0]), "=r"((r)[1]), "=r"((r)[2]), "=r"((r)[3]) : "r"(addr))

#define MMA16816(c, a, b0, b1) \
    asm volatile("mma.sync.aligned.m16n8k16.row.col.f32.bf16.bf16.f32 " \
        "{%0,%1,%2,%3},{%4,%5,%6,%7},{%8,%9},{%0,%1,%2,%3};" \
        : "+f"((c)[0]), "+f"((c)[1]), "+f"((c)[2]), "+f"((c)[3]) \
        : "r"((a)[0]), "r"((a)[1]), "r"((a)[2]), "r"((a)[3]), "r"(b0), "r"(b1))

// ---------------------------------------------------------------------------
// split fp32 -> bf16 hi/lo (vectorized by 4)
// ---------------------------------------------------------------------------
__global__ void split_f32(const float* __restrict__ s,
                          __nv_bfloat16* __restrict__ hi,
                          __nv_bfloat16* __restrict__ lo, int n4)
{
    int i = blockIdx.x * blockDim.x + threadIdx.x;
    if (i >= n4) return;
    float4 v = ((const float4*)s)[i];
    __nv_bfloat16 h0 = __float2bfloat16_rn(v.x);
    __nv_bfloat16 h1 = __float2bfloat16_rn(v.y);
    __nv_bfloat16 h2 = __float2bfloat16_rn(v.z);
    __nv_bfloat16 h3 = __float2bfloat16_rn(v.w);
    __nv_bfloat16 l0 = __float2bfloat16_rn(v.x - __bfloat162float(h0));
    __nv_bfloat16 l1 = __float2bfloat16_rn(v.y - __bfloat162float(h1));
    __nv_bfloat16 l2 = __float2bfloat16_rn(v.z - __bfloat162float(h2));
    __nv_bfloat16 l3 = __float2bfloat16_rn(v.w - __bfloat162float(h3));
    __nv_bfloat162* ph = (__nv_bfloat162*)hi;
    __nv_bfloat162* pl = (__nv_bfloat162*)lo;
    ph[i * 2 + 0] = __nv_bfloat162(h0, h1);
    ph[i * 2 + 1] = __nv_bfloat162(h2, h3);
    pl[i * 2 + 0] = __nv_bfloat162(l0, l1);
    pl[i * 2 + 1] = __nv_bfloat162(l2, l3);
}

// ---------------------------------------------------------------------------
// transpose + split: W[K][N] fp32 -> WT[N][K] bf16 hi/lo
// ---------------------------------------------------------------------------
__global__ void tsplit(const float* __restrict__ W,
                       __nv_bfloat16* __restrict__ hi,
                       __nv_bfloat16* __restrict__ lo, int K, int N)
{
    __shared__ float t[32][33];
    int n0 = blockIdx.x * 32, k0 = blockIdx.y * 32;
    int tx = threadIdx.x, ty = threadIdx.y;
#pragma unroll
    for (int i = 0; i < 4; i++)
        t[ty + 8 * i][tx] = W[(size_t)(k0 + ty + 8 * i) * N + n0 + tx];
    __syncthreads();
#pragma unroll
    for (int i = 0; i < 4; i++) {
        float v = t[tx][ty + 8 * i];
        __nv_bfloat16 h = __float2bfloat16_rn(v);
        size_t off = (size_t)(n0 + ty + 8 * i) * K + k0 + tx;
        hi[off] = h;
        lo[off] = __float2bfloat16_rn(v - __bfloat162float(h));
    }
}

// ---------------------------------------------------------------------------
// HMMA GEMM (from R3, passing): C = Ahi@Bhi^T + Ahi@Blo^T + Alo@Bhi^T + bias
// ---------------------------------------------------------------------------
__global__ __launch_bounds__(256, 1) void gemm_mma(
    int M, int N,
    const __nv_bfloat16* __restrict__ Ahi, const __nv_bfloat16* __restrict__ Alo,
    const __nv_bfloat16* __restrict__ Bhi, const __nv_bfloat16* __restrict__ Blo,
    const float* __restrict__ bias, float* __restrict__ C)
{
    constexpr int KD = 2048;
    constexpr int NCHUNK = KD / 64;
    extern __shared__ char dsm[];
    uint32_t sbase = (cvta_s(dsm) + 1023) & ~1023u;

    const int tid = threadIdx.x;
    const int wid = tid >> 5, lane = tid & 31;
    const int wm = wid >> 2, wn = wid & 3;
    const int m0 = blockIdx.y * 128, n0 = blockIdx.x * 128;

    uint32_t dsts[4];
    size_t gA[4], gB[4];
#pragma unroll
    for (int p = 0; p < 4; p++) {
        int idx = tid + p * 256;
        int row = idx >> 3, ch = idx & 7;
        dsts[p] = row * 128 + ((ch ^ (row & 7)) * 16);
        gA[p] = (size_t)(m0 + row) * KD + ch * 8;
        gB[p] = (size_t)(n0 + row) * KD + ch * 8;
    }

    const int arow = (lane & 7) + ((lane >> 3) & 1) * 8;
    const int acb  = lane >> 4;
    const int brow = (lane & 7) + (lane >> 4) * 8;
    const int bcb  = (lane >> 3) & 1;

    float acc[4][4][4];
#pragma unroll
    for (int i = 0; i < 4; i++)
#pragma unroll
        for (int j = 0; j < 4; j++) {
            acc[i][j][0] = 0.f; acc[i][j][1] = 0.f;
            acc[i][j][2] = 0.f; acc[i][j][3] = 0.f;
        }

#pragma unroll
    for (int p = 0; p < 4; p++) {
        uint32_t st = sbase;
        cp16(st +     0 + dsts[p], Ahi + gA[p]);
        cp16(st + 16384 + dsts[p], Alo + gA[p]);
        cp16(st + 32768 + dsts[p], Bhi + gB[p]);
        cp16(st + 49152 + dsts[p], Blo + gB[p]);
    }
    CP_COMMIT();

    for (int c = 0; c < NCHUNK; c++) {
        if (c + 1 < NCHUNK) {
            uint32_t st = sbase + ((c + 1) & 1) * 65536;
            int k0 = (c + 1) * 64;
#pragma unroll
            for (int p = 0; p < 4; p++) {
                cp16(st +     0 + dsts[p], Ahi + gA[p] + k0);
                cp16(st + 16384 + dsts[p], Alo + gA[p] + k0);
                cp16(st + 32768 + dsts[p], Bhi + gB[p] + k0);
                cp16(st + 49152 + dsts[p], Blo + gB[p] + k0);
            }
            CP_COMMIT();
            CP_WAIT(1);
        } else {
            CP_WAIT(0);
        }
        __syncthreads();

        uint32_t st = sbase + (c & 1) * 65536;
        uint32_t aHiB = st, aLoB = st + 16384, bHiB = st + 32768, bLoB = st + 49152;

#pragma unroll
        for (int ks = 0; ks < 4; ks++) {
            uint32_t ahi[4][4], alo[4][4], bhi[2][4], blo[2][4];
#pragma unroll
            for (int mt = 0; mt < 4; mt++) {
                int r = wm * 64 + mt * 16 + arow;
                uint32_t off = r * 128 + (((2 * ks + acb) ^ (r & 7)) * 16);
                LDSM4(ahi[mt], aHiB + off);
            }
#pragma unroll
            for (int np = 0; np < 2; np++) {
                int r = wn * 32 + np * 16 + brow;
                uint32_t off = r * 128 + (((2 * ks + bcb) ^ (r & 7)) * 16);
                LDSM4(bhi[np], bHiB + off);
            }
#pragma unroll
            for (int mt = 0; mt < 4; mt++)
#pragma unroll
                for (int nt = 0; nt < 4; nt++)
                    MMA16816(acc[mt][nt], ahi[mt], bhi[nt >> 1][(nt & 1) * 2],
                             bhi[nt >> 1][(nt & 1) * 2 + 1]);
#pragma unroll
            for (int np = 0; np < 2; np++) {
                int r = wn * 32 + np * 16 + brow;
                uint32_t off = r * 128 + (((2 * ks + bcb) ^ (r & 7)) * 16);
                LDSM4(blo[np], bLoB + off);
            }
#pragma unroll
            for (int mt = 0; mt < 4; mt++)
#pragma unroll
                for (int nt = 0; nt < 4; nt++)
                    MMA16816(acc[mt][nt], ahi[mt], blo[nt >> 1][(nt & 1) * 2],
                             blo[nt >> 1][(nt & 1) * 2 + 1]);
#pragma unroll
            for (int mt = 0; mt < 4; mt++) {
                int r = wm * 64 + mt * 16 + arow;
                uint32_t off = r * 128 + (((2 * ks + acb) ^ (r & 7)) * 16);
                LDSM4(alo[mt], aLoB + off);
            }
#pragma unroll
            for (int mt = 0; mt < 4; mt++)
#pragma unroll
                for (int nt = 0; nt < 4; nt++)
                    MMA16816(acc[mt][nt], alo[mt], bhi[nt >> 1][(nt & 1) * 2],
                             bhi[nt >> 1][(nt & 1) * 2 + 1]);
        }
        __syncthreads();
    }

#pragma unroll
    for (int mt = 0; mt < 4; mt++) {
        int r0 = m0 + wm * 64 + mt * 16 + (lane >> 2);
#pragma unroll
        for (int nt = 0; nt < 4; nt++) {
            int cc = n0 + wn * 32 + nt * 8 + (lane & 3) * 2;
            float b0 = bias[cc], b1 = bias[cc + 1];
            float2 v0 = make_float2(acc[mt][nt][0] + b0, acc[mt][nt][1] + b1);
            float2 v1 = make_float2(acc[mt][nt][2] + b0, acc[mt][nt][3] + b1);
            *(float2*)(C + (size_t)r0 * N + cc) = v0;
            *(float2*)(C + (size_t)(r0 + 8) * N + cc) = v1;
        }
    }
}

// ---------------------------------------------------------------------------
// RoPE + pack to [b,h,t,d] bf16 hi/lo
// ---------------------------------------------------------------------------
__global__ void rope_pack(const float* __restrict__ X,
                          __nv_bfloat16* __restrict__ hi,
                          __nv_bfloat16* __restrict__ lo, int nh)
{
    int idx = blockIdx.x * blockDim.x + threadIdx.x;
    int total = MROWS * nh * 64;
    if (idx >= total) return;
    int d = idx & 63;
    int h = (idx >> 6) % nh;
    int r = idx / (64 * nh);
    int t = r & (TSEQ - 1);
    int b = r >> 11;

    const float* p = X + (size_t)r * (nh * DHEAD) + h * DHEAD + d;
    float x1 = p[0], x2 = p[64];
    float inv = powf(10000.f, -(float)d * (1.f / 64.f));
    float s, c;
    sincosf((float)t * inv, &s, &c);
    float y1 = x1 * c - x2 * s;
    float y2 = x1 * s + x2 * c;

    size_t orow = ((size_t)(b * nh + h) * TSEQ + t) * DHEAD;
    __nv_bfloat16 h1 = __float2bfloat16_rn(y1);
    __nv_bfloat16 h2 = __float2bfloat16_rn(y2);
    hi[orow + d]      = h1;
    lo[orow + d]      = __float2bfloat16_rn(y1 - __bfloat162float(h1));
    hi[orow + 64 + d] = h2;
    lo[orow + 64 + d] = __float2bfloat16_rn(y2 - __bfloat162float(h2));
}

// ---------------------------------------------------------------------------
// V pack: [b,t,g,d] fp32 -> [b,g,t,d] bf16 hi/lo (vectorized by 4)
// ---------------------------------------------------------------------------
__global__ void pack_v(const float* __restrict__ V,
                       __nv_bfloat16* __restrict__ hi,
                       __nv_bfloat16* __restrict__ lo)
{
    int idx = blockIdx.x * blockDim.x + threadIdx.x;  // over MROWS*KVC/4
    if (idx >= MROWS * KVC / 4) return;
    int d4 = idx & 31;
    int g = (idx >> 5) & 3;
    int r = idx >> 7;
    int t = r & (TSEQ - 1);
    int b = r >> 11;

    float4 v = *(const float4*)(V + (size_t)r * KVC + g * DHEAD + d4 * 4);
    size_t o = ((size_t)(b * NGROUP + g) * TSEQ + t) * DHEAD + d4 * 4;
    __nv_bfloat16 h0 = __float2bfloat16_rn(v.x);
    __nv_bfloat16 h1 = __float2bfloat16_rn(v.y);
    __nv_bfloat16 h2 = __float2bfloat16_rn(v.z);
    __nv_bfloat16 h3 = __float2bfloat16_rn(v.w);
    *(__nv_bfloat162*)(hi + o)     = __nv_bfloat162(h0, h1);
    *(__nv_bfloat162*)(hi + o + 2) = __nv_bfloat162(h2, h3);
    *(__nv_bfloat162*)(lo + o)     = __nv_bfloat162(
        __float2bfloat16_rn(v.x - __bfloat162float(h0)),
        __float2bfloat16_rn(v.y - __bfloat162float(h1)));
    *(__nv_bfloat162*)(lo + o + 2) = __nv_bfloat162(
        __float2bfloat16_rn(v.z - __bfloat162float(h2)),
        __float2bfloat16_rn(v.w - __bfloat162float(h3)));
}

// ---------------------------------------------------------------------------
// HMMA flash attention. grid (32 qtiles, 32 bh), 128 threads (4 warps x 16 q).
// KV tile 64. bf16 hi/lo 3-term products for QK^T and PV.
// Writes ohi/olo ([b,t,h,d] row = b*T+t, col = h*128+d) directly.
// ---------------------------------------------------------------------------
__global__ __launch_bounds__(128, 1) void attn_mma(
    const __nv_bfloat16* __restrict__ qhi, const __nv_bfloat16* __restrict__ qlo,
    const __nv_bfloat16* __restrict__ khi, const __nv_bfloat16* __restrict__ klo,
    const __nv_bfloat16* __restrict__ vhi, const __nv_bfloat16* __restrict__ vlo,
    __nv_bfloat16* __restrict__ ohi, __nv_bfloat16* __restrict__ olo)
{
    extern __shared__ char sm[];
    uint32_t sb = (cvta_s(sm) + 255) & ~255u;
    const uint32_t sQh = sb,          sQl = sb + 16384;
    const uint32_t sKh = sb + 32768,  sKl = sb + 49152;
    const uint32_t sVh = sb + 65536,  sVl = sb + 81920;

    const int tid = threadIdx.x, w = tid >> 5, lane = tid & 31;
    const int b = blockIdx.y >> 4, h = blockIdx.y & 15, g = h >> 2;
    const int qs = blockIdx.x * 64;

    // Q tile load (16KB hi + 16KB lo)
    {
        size_t qb = ((size_t)(b * NHEAD + h) * TSEQ + qs) * DHEAD;
#pragma unroll
        for (int p = 0; p < 8; p++) {
            int idx = tid + p * 128;
            int row = idx >> 4, ch = idx & 15;
            uint32_t d = row * 256 + ((ch ^ (row & 7)) << 4);
            size_t s = qb + (size_t)row * DHEAD + ch * 8;
            cp16(sQh + d, qhi + s);
            cp16(sQl + d, qlo + s);
        }
    }
    CP_COMMIT();

    int t0 = qs - SWIN; if (t0 < 0) t0 = 0; t0 &= ~63;
    const int sink_extra = (t0 > 0) ? 1 : 0;
    const int ntiles = sink_extra + (qs + 64 - t0) / 64;

    float o[16][4];
#pragma unroll
    for (int i = 0; i < 16; i++) { o[i][0] = 0.f; o[i][1] = 0.f; o[i][2] = 0.f; o[i][3] = 0.f; }
    float m0 = -1e30f, m1 = -1e30f, l0 = 0.f, l1 = 0.f;

    const int arow = (lane & 7) + ((lane >> 3) & 1) * 8;
    const int acb  = lane >> 4;
    const int brow = (lane & 7) + (lane >> 4) * 8;
    const int bcb  = (lane >> 3) & 1;
    const int vr_i = ((lane >> 3) & 1) * 8 + (lane & 7);
    const int vc_i = lane >> 4;
    const float scale = 0.08838834764831845f;
    const int i0 = qs + w * 16 + (lane >> 2);
    const int i1 = i0 + 8;
    const int cbs = (lane & 3) * 2;

    for (int it = 0; it < ntiles; it++) {
        const bool sink_only = (sink_extra && it == 0);
        const int ts = sink_only ? 0 : t0 + (it - sink_extra) * 64;
        const int nkt = sink_only ? 1 : 4;

        __syncthreads();
        {
            size_t kb = ((size_t)(b * NGROUP + g) * TSEQ + ts) * DHEAD;
#pragma unroll
            for (int p = 0; p < 8; p++) {
                int idx = tid + p * 128;
                int row = idx >> 4, ch = idx & 15;
                uint32_t d = row * 256 + ((ch ^ (row & 7)) << 4);
                size_t s = kb + (size_t)row * DHEAD + ch * 8;
                cp16(sKh + d, khi + s);
                cp16(sKl + d, klo + s);
                cp16(sVh + d, vhi + s);
                cp16(sVl + d, vlo + s);
            }
        }
        CP_COMMIT();
        CP_WAIT(0);
        __syncthreads();

        // S = Q @ K^T (3-term hi/lo)
        float sc[8][4];
#pragma unroll
        for (int i = 0; i < 8; i++) { sc[i][0] = 0.f; sc[i][1] = 0.f; sc[i][2] = 0.f; sc[i][3] = 0.f; }

#pragma unroll
        for (int kc = 0; kc < 8; kc++) {
            int qr = w * 16 + arow;
            uint32_t aoff = qr * 256 + (((2 * kc + acb) ^ (qr & 7)) << 4);
            uint32_t ah[4], al[4];
            LDSM4(ah, sQh + aoff);
            LDSM4(al, sQl + aoff);
            for (int n2 = 0; n2 < nkt; n2++) {
                int kr = n2 * 16 + brow;
                uint32_t boff = kr * 256 + (((2 * kc + bcb) ^ (kr & 7)) << 4);
                uint32_t bh_[4], bl_[4];
                LDSM4(bh_, sKh + boff);
                LDSM4(bl_, sKl + boff);
                MMA16816(sc[2 * n2],     ah, bh_[0], bh_[1]);
                MMA16816(sc[2 * n2],     ah, bl_[0], bl_[1]);
                MMA16816(sc[2 * n2],     al, bh_[0], bh_[1]);
                MMA16816(sc[2 * n2 + 1], ah, bh_[2], bh_[3]);
                MMA16816(sc[2 * n2 + 1], ah, bl_[2], bl_[3]);
                MMA16816(sc[2 * n2 + 1], al, bh_[2], bh_[3]);
            }
        }

        // mask + scale + row max
        float rm0 = -1e30f, rm1 = -1e30f;
#pragma unroll
        for (int nt = 0; nt < 8; nt++) {
            int j0 = ts + nt * 8 + cbs, j1 = j0 + 1;
            sc[nt][0] = (j0 <= i0 && (j0 >= i0 - SWIN || j0 < SINK)) ? sc[nt][0] * scale : -1e30f;
            sc[nt][1] = (j1 <= i0 && (j1 >= i0 - SWIN || j1 < SINK)) ? sc[nt][1] * scale : -1e30f;
            sc[nt][2] = (j0 <= i1 && (j0 >= i1 - SWIN || j0 < SINK)) ? sc[nt][2] * scale : -1e30f;
            sc[nt][3] = (j1 <= i1 && (j1 >= i1 - SWIN || j1 < SINK)) ? sc[nt][3] * scale : -1e30f;
            rm0 = fmaxf(rm0, fmaxf(sc[nt][0], sc[nt][1]));
            rm1 = fmaxf(rm1, fmaxf(sc[nt][2], sc[nt][3]));
        }
        rm0 = fmaxf(rm0, __shfl_xor_sync(0xffffffffu, rm0, 1));
        rm0 = fmaxf(rm0, __shfl_xor_sync(0xffffffffu, rm0, 2));
        rm1 = fmaxf(rm1, __shfl_xor_sync(0xffffffffu, rm1, 1));
        rm1 = fmaxf(rm1, __shfl_xor_sync(0xffffffffu, rm1, 2));
        float mn0 = fmaxf(m0, rm0), mn1 = fmaxf(m1, rm1);
        float c0 = __expf(m0 - mn0), c1 = __expf(m1 - mn1);
        m0 = mn0; m1 = mn1;

#pragma unroll
        for (int nd = 0; nd < 16; nd++) {
            o[nd][0] *= c0; o[nd][1] *= c0; o[nd][2] *= c1; o[nd][3] *= c1;
        }

        float rs0 = 0.f, rs1 = 0.f;
        for (int k2 = 0; k2 < nkt; k2++) {
            // exp + bf16 hi/lo pack for P tiles 2*k2, 2*k2+1
            uint32_t aP[4], aPl[4];
#pragma unroll
            for (int q2 = 0; q2 < 2; q2++) {
                int nt = 2 * k2 + q2;
                float p00 = __expf(sc[nt][0] - mn0), p01 = __expf(sc[nt][1] - mn0);
                float p10 = __expf(sc[nt][2] - mn1), p11 = __expf(sc[nt][3] - mn1);
                rs0 += p00 + p01; rs1 += p10 + p11;
                __nv_bfloat162 h0v = __floats2bfloat162_rn(p00, p01);
                __nv_bfloat162 h1v = __floats2bfloat162_rn(p10, p11);
                __nv_bfloat162 l0v = __floats2bfloat162_rn(
                    p00 - __bfloat162float(h0v.x), p01 - __bfloat162float(h0v.y));
                __nv_bfloat162 l1v = __floats2bfloat162_rn(
                    p10 - __bfloat162float(h1v.x), p11 - __bfloat162float(h1v.y));
                aP[2 * q2]      = *(uint32_t*)&h0v;
                aP[2 * q2 + 1]  = *(uint32_t*)&h1v;
                aPl[2 * q2]     = *(uint32_t*)&l0v;
                aPl[2 * q2 + 1] = *(uint32_t*)&l1v;
            }
            // fix a-frag order: a = {rowsLo kLo, rowsHi kLo, rowsLo kHi, rowsHi kHi}
            // tiles: nt=2k2 covers k0-7 -> regs {aP[0],aP[1]}; nt=2k2+1 -> {aP[2],aP[3]}
            // (already in that order)
#pragma unroll
            for (int ndp = 0; ndp < 8; ndp++) {
                int vr = k2 * 16 + vr_i;
                int vc = ndp * 2 + vc_i;
                uint32_t voff = vr * 256 + ((vc ^ (vr & 7)) << 4);
                uint32_t bv[4], bvl[4];
                LDSM4T(bv,  sVh + voff);
                LDSM4T(bvl, sVl + voff);
                MMA16816(o[ndp * 2],     aP,  bv[0],  bv[1]);
                MMA16816(o[ndp * 2],     aP,  bvl[0], bvl[1]);
                MMA16816(o[ndp * 2],     aPl, bv[0],  bv[1]);
                MMA16816(o[ndp * 2 + 1], aP,  bv[2],  bv[3]);
                MMA16816(o[ndp * 2 + 1], aP,  bvl[2], bvl[3]);
                MMA16816(o[ndp * 2 + 1], aPl, bv[2],  bv[3]);
            }
        }
        rs0 += __shfl_xor_sync(0xffffffffu, rs0, 1);
        rs0 += __shfl_xor_sync(0xffffffffu, rs0, 2);
        rs1 += __shfl_xor_sync(0xffffffffu, rs1, 1);
        rs1 += __shfl_xor_sync(0xffffffffu, rs1, 2);
        l0 = l0 * c0 + rs0;
        l1 = l1 * c1 + rs1;
    }

    // epilogue: O/l -> bf16 hi/lo, layout [b*T+t, h*128+d]
    float il0 = 1.f / l0, il1 = 1.f / l1;
    size_t or0 = (size_t)(b * TSEQ + qs + w * 16 + (lane >> 2)) * CEMB + h * DHEAD;
    size_t or1 = or0 + (size_t)8 * CEMB;
#pragma unroll
    for (int nd = 0; nd < 16; nd++) {
        int col = nd * 8 + cbs;
        float v0 = o[nd][0] * il0, v1 = o[nd][1] * il0;
        float v2 = o[nd][2] * il1, v3 = o[nd][3] * il1;
        __nv_bfloat162 h0v = __floats2bfloat162_rn(v0, v1);
        __nv_bfloat162 h1v = __floats2bfloat162_rn(v2, v3);
        __nv_bfloat162 l0v = __floats2bfloat162_rn(
            v0 - __bfloat162float(h0v.x), v1 - __bfloat162float(h0v.y));
        __nv_bfloat162 l1v = __floats2bfloat162_rn(
            v2 - __bfloat162float(h1v.x), v3 - __bfloat162float(h1v.y));
        *(__nv_bfloat162*)(ohi + or0 + col) = h0v;
        *(__nv_bfloat162*)(olo + or0 + col) = l0v;
        *(__nv_bfloat162*)(ohi + or1 + col) = h1v;
        *(__nv_bfloat162*)(olo + or1 + col) = l1v;
    }
}

// ---------------------------------------------------------------------------
extern "C" void kernel_launch(void* const* d_in, const int* in_sizes, int n_in,
                              void* d_out, int out_size)
{
    const float* x  = (const float*)d_in[0];
    const float* Wq = (const float*)d_in[1];
    const float* bq = (const float*)d_in[2];
    const float* Wk = (const float*)d_in[3];
    const float* bk = (const float*)d_in[4];
    const float* Wv = (const float*)d_in[5];
    const float* bv = (const float*)d_in[6];
    const float* Wo = (const float*)d_in[7];
    const float* bo = (const float*)d_in[8];
    float* out = (float*)d_out;

    float *Q, *K, *V;
    cudaGetSymbolAddress((void**)&Q, g_Q);
    cudaGetSymbolAddress((void**)&K, g_K);
    cudaGetSymbolAddress((void**)&V, g_V);
    __nv_bfloat16 *xhi, *xlo, *ohi, *olo, *qhi, *qlo, *khi, *klo, *vhi, *vlo;
    __nv_bfloat16 *wqh, *wql, *wkh, *wkl, *wvh, *wvl, *woh, *wol;
    cudaGetSymbolAddress((void**)&xhi, g_xhi);
    cudaGetSymbolAddress((void**)&xlo, g_xlo);
    cudaGetSymbolAddress((void**)&ohi, g_ohi);
    cudaGetSymbolAddress((void**)&olo, g_olo);
    cudaGetSymbolAddress((void**)&qhi, g_qhi);
    cudaGetSymbolAddress((void**)&qlo, g_qlo);
    cudaGetSymbolAddress((void**)&khi, g_khi);
    cudaGetSymbolAddress((void**)&klo, g_klo);
    cudaGetSymbolAddress((void**)&vhi, g_vhi);
    cudaGetSymbolAddress((void**)&vlo, g_vlo);
    cudaGetSymbolAddress((void**)&wqh, g_WqT_hi);
    cudaGetSymbolAddress((void**)&wql, g_WqT_lo);
    cudaGetSymbolAddress((void**)&wkh, g_WkT_hi);
    cudaGetSymbolAddress((void**)&wkl, g_WkT_lo);
    cudaGetSymbolAddress((void**)&wvh, g_WvT_hi);
    cudaGetSymbolAddress((void**)&wvl, g_WvT_lo);
    cudaGetSymbolAddress((void**)&woh, g_WoT_hi);
    cudaGetSymbolAddress((void**)&wol, g_WoT_lo);

    const int GEMM_SMEM = 132096;
    cudaFuncSetAttribute(gemm_mma, cudaFuncAttributeMaxDynamicSharedMemorySize, GEMM_SMEM);
    const int ATTN_SMEM = 98560;
    cudaFuncSetAttribute(attn_mma, cudaFuncAttributeMaxDynamicSharedMemorySize, ATTN_SMEM);

    // input splits / weight transposes
    {
        int n4 = (MROWS * CEMB) / 4;
        split_f32<<<(n4 + 255) / 256, 256>>>(x, xhi, xlo, n4);
    }
    tsplit<<<dim3(CEMB / 32, CEMB / 32), dim3(32, 8)>>>(Wq, wqh, wql, CEMB, CEMB);
    tsplit<<<dim3(KVC  / 32, CEMB / 32), dim3(32, 8)>>>(Wk, wkh, wkl, CEMB, KVC);
    tsplit<<<dim3(KVC  / 32, CEMB / 32), dim3(32, 8)>>>(Wv, wvh, wvl, CEMB, KVC);
    tsplit<<<dim3(CEMB / 32, CEMB / 32), dim3(32, 8)>>>(Wo, woh, wol, CEMB, CEMB);

    // QKV projections (tensor cores)
    gemm_mma<<<dim3(CEMB / 128, MROWS / 128), 256, GEMM_SMEM>>>(
        MROWS, CEMB, xhi, xlo, wqh, wql, bq, Q);
    gemm_mma<<<dim3(KVC / 128, MROWS / 128), 256, GEMM_SMEM>>>(
        MROWS, KVC, xhi, xlo, wkh, wkl, bk, K);
    gemm_mma<<<dim3(KVC / 128, MROWS / 128), 256, GEMM_SMEM>>>(
        MROWS, KVC, xhi, xlo, wvh, wvl, bv, V);

    // RoPE + pack to attention layouts
    rope_pack<<<(MROWS * NHEAD * 64) / 256, 256>>>(Q, qhi, qlo, NHEAD);
    rope_pack<<<(MROWS * NGROUP * 64) / 256, 256>>>(K, khi, klo, NGROUP);
    pack_v<<<(MROWS * KVC / 4 + 255) / 256, 256>>>(V, vhi, vlo);

    // flash attention (tensor cores)
    attn_mma<<<dim3(TSEQ / 64, 2 * NHEAD), 128, ATTN_SMEM>>>(
        qhi, qlo, khi, klo, vhi, vlo, ohi, olo);

    // output projection
    gemm_mma<<<dim3(CEMB / 128, MROWS / 128), 256, GEMM_SMEM>>>(
        MROWS, CEMB, ohi, olo, woh, wol, bo, out);
}

// round 5
// speedup vs baseline: 5.2089x; 1.0519x over previous
#include <cuda_runtime.h>
#include <cuda_bf16.h>
#include <math.h>
#include <stdint.h>

// Problem constants
#define MROWS 4096   // B*T
#define CEMB  2048
#define TSEQ  2048
#define NHEAD 16
#define NGROUP 4
#define DHEAD 128
#define KVC   512
#define SWIN  512
#define SINK  4
#define NQKV  3072   // 2048 + 512 + 512

// fp32 scratch
__device__ float g_Q[(size_t)MROWS * CEMB];
__device__ float g_K[(size_t)MROWS * KVC];
__device__ float g_V[(size_t)MROWS * KVC];

// bf16 split scratch
__device__ __nv_bfloat16 g_xhi[(size_t)MROWS * CEMB];
__device__ __nv_bfloat16 g_xlo[(size_t)MROWS * CEMB];
__device__ __nv_bfloat16 g_ohi[(size_t)MROWS * CEMB];
__device__ __nv_bfloat16 g_olo[(size_t)MROWS * CEMB];
__device__ __nv_bfloat16 g_qhi[(size_t)MROWS * CEMB];   // [b,h,t,d]
__device__ __nv_bfloat16 g_qlo[(size_t)MROWS * CEMB];
__device__ __nv_bfloat16 g_khi[(size_t)MROWS * KVC];    // [b,g,t,d]
__device__ __nv_bfloat16 g_klo[(size_t)MROWS * KVC];
__device__ __nv_bfloat16 g_vhi[(size_t)MROWS * KVC];
__device__ __nv_bfloat16 g_vlo[(size_t)MROWS * KVC];
__device__ __nv_bfloat16 g_WT_hi[(size_t)NQKV * CEMB];  // packed Wq|Wk|Wv, [N,K]
__device__ __nv_bfloat16 g_WT_lo[(size_t)NQKV * CEMB];
__device__ __nv_bfloat16 g_WoT_hi[(size_t)CEMB * CEMB];
__device__ __nv_bfloat16 g_WoT_lo[(size_t)CEMB * CEMB];

// ---------------------------------------------------------------------------
// helpers
// ---------------------------------------------------------------------------
__device__ __forceinline__ uint32_t cvta_s(const void* p) {
    return (uint32_t)__cvta_generic_to_shared(p);
}
__device__ __forceinline__ void cp16(uint32_t dst, const void* src) {
    asm volatile("cp.async.cg.shared.global [%0], [%1], 16;\n" :: "r"(dst), "l"(src));
}
#define CP_COMMIT() asm volatile("cp.async.commit_group;\n" ::: "memory")
#define CP_WAIT(n)  asm volatile("cp.async.wait_group %0;\n" :: "n"(n) : "memory")

#define LDSM4(r, addr) \
    asm volatile("ldmatrix.sync.aligned.m8n8.x4.shared.b16 {%0,%1,%2,%3}, [%4];" \
        : "=r"((r)[0]), "=r"((r)[1]), "=r"((r)[2]), "=r"((r)[3]) : "r"(addr))

#define LDSM4T(r, addr) \
    asm volatile("ldmatrix.sync.aligned.m8n8.x4.trans.shared.b16 {%0,%1,%2,%3}, [%4];" \
        : "=r"((r)[0]), "=r"((r)[1]), "=r"((r)[2]), "=r"((r)[3]) : "r"(addr))

#define MMA16816(c, a, b0, b1) \
    asm volatile("mma.sync.aligned.m16n8k16.row.col.f32.bf16.bf16.f32 " \
        "{%0,%1,%2,%3},{%4,%5,%6,%7},{%8,%9},{%0,%1,%2,%3};" \
        : "+f"((c)[0]), "+f"((c)[1]), "+f"((c)[2]), "+f"((c)[3]) \
        : "r"((a)[0]), "r"((a)[1]), "r"((a)[2]), "r"((a)[3]), "r"(b0), "r"(b1))

// 64B-row swizzled address (BK=32 tiles): row r (0..127), 16B chunk c4 (0..3)
__device__ __forceinline__ uint32_t adr32(int r, int c4) {
    return (uint32_t)((r >> 1) * 128 + (((((r & 1) << 2) | c4) ^ ((r >> 1) & 7)) << 4));
}
// 256B-row swizzled address (attention tiles): row r, 16B chunk c (0..15)
__device__ __forceinline__ uint32_t adr128(int r, int c) {
    return (uint32_t)(r * 256 + ((c ^ (r & 7)) << 4));
}

// ---------------------------------------------------------------------------
// split fp32 -> bf16 hi/lo (vectorized by 4)
// ---------------------------------------------------------------------------
__global__ void split_f32(const float* __restrict__ s,
                          __nv_bfloat16* __restrict__ hi,
                          __nv_bfloat16* __restrict__ lo, int n4)
{
    int i = blockIdx.x * blockDim.x + threadIdx.x;
    if (i >= n4) return;
    float4 v = ((const float4*)s)[i];
    __nv_bfloat16 h0 = __float2bfloat16_rn(v.x);
    __nv_bfloat16 h1 = __float2bfloat16_rn(v.y);
    __nv_bfloat16 h2 = __float2bfloat16_rn(v.z);
    __nv_bfloat16 h3 = __float2bfloat16_rn(v.w);
    __nv_bfloat162* ph = (__nv_bfloat162*)hi;
    __nv_bfloat162* pl = (__nv_bfloat162*)lo;
    ph[i * 2 + 0] = __nv_bfloat162(h0, h1);
    ph[i * 2 + 1] = __nv_bfloat162(h2, h3);
    pl[i * 2 + 0] = __nv_bfloat162(
        __float2bfloat16_rn(v.x - __bfloat162float(h0)),
        __float2bfloat16_rn(v.y - __bfloat162float(h1)));
    pl[i * 2 + 1] = __nv_bfloat162(
        __float2bfloat16_rn(v.z - __bfloat162float(h2)),
        __float2bfloat16_rn(v.w - __bfloat162float(h3)));
}

// ---------------------------------------------------------------------------
// transpose + split: W[K][N] fp32 -> WT[N][K] bf16 hi/lo
// ---------------------------------------------------------------------------
__global__ void tsplit(const float* __restrict__ W,
                       __nv_bfloat16* __restrict__ hi,
                       __nv_bfloat16* __restrict__ lo, int K, int N)
{
    __shared__ float t[32][33];
    int n0 = blockIdx.x * 32, k0 = blockIdx.y * 32;
    int tx = threadIdx.x, ty = threadIdx.y;
#pragma unroll
    for (int i = 0; i < 4; i++)
        t[ty + 8 * i][tx] = W[(size_t)(k0 + ty + 8 * i) * N + n0 + tx];
    __syncthreads();
#pragma unroll
    for (int i = 0; i < 4; i++) {
        float v = t[tx][ty + 8 * i];
        __nv_bfloat16 h = __float2bfloat16_rn(v);
        size_t off = (size_t)(n0 + ty + 8 * i) * K + k0 + tx;
        hi[off] = h;
        lo[off] = __float2bfloat16_rn(v - __bfloat162float(h));
    }
}

// ---------------------------------------------------------------------------
// HMMA GEMM, 3-term bf16: C = Ahi@Bhi^T + Ahi@Blo^T + Alo@Bhi^T + bias
// A: [4096, 2048], B: [Ntot, 2048] (Ntot = gridDim.x*128).
// CTA 128x128, BK=32, 3-stage cp.async, 2 CTAs/SM.
// Epilogue routes by n0 into (C0,2048) / (C1,512) / (C2,512).
// ---------------------------------------------------------------------------
__global__ __launch_bounds__(256, 2) void gemm_mma(
    const __nv_bfloat16* __restrict__ Ahi, const __nv_bfloat16* __restrict__ Alo,
    const __nv_bfloat16* __restrict__ Bhi, const __nv_bfloat16* __restrict__ Blo,
    float* __restrict__ C0, const float* __restrict__ b0,
    float* __restrict__ C1, const float* __restrict__ b1,
    float* __restrict__ C2, const float* __restrict__ b2)
{
    constexpr int KD = 2048, NCHUNK = 64, STG = 32768;
    extern __shared__ char dsm[];
    uint32_t sbase = (cvta_s(dsm) + 1023) & ~1023u;

    const int tid = threadIdx.x;
    const int wid = tid >> 5, lane = tid & 31;
    const int wm = wid >> 2, wn = wid & 3;
    const int m0 = blockIdx.y * 128, n0 = blockIdx.x * 128;

    // cp.async slots: 2 chunks-of-16B per thread per array per stage
    uint32_t dsts[2];
    size_t gA[2], gB[2];
#pragma unroll
    for (int p = 0; p < 2; p++) {
        int idx = tid + p * 256;
        int r = idx >> 2, c = idx & 3;
        dsts[p] = adr32(r, c);
        gA[p] = (size_t)(m0 + r) * KD + c * 8;
        gB[p] = (size_t)(n0 + r) * KD + c * 8;
    }

    const int arow = (lane & 7) + ((lane >> 3) & 1) * 8;
    const int acb  = lane >> 4;
    const int brow = (lane & 7) + (lane >> 4) * 8;
    const int bcb  = (lane >> 3) & 1;

    float acc[4][4][4];
#pragma unroll
    for (int i = 0; i < 4; i++)
#pragma unroll
        for (int j = 0; j < 4; j++) {
            acc[i][j][0] = 0.f; acc[i][j][1] = 0.f;
            acc[i][j][2] = 0.f; acc[i][j][3] = 0.f;
        }

    // prefetch chunks 0, 1
#pragma unroll
    for (int ch = 0; ch < 2; ch++) {
        uint32_t st = sbase + ch * STG;
        int k0 = ch * 32;
#pragma unroll
        for (int p = 0; p < 2; p++) {
            cp16(st +     0 + dsts[p], Ahi + gA[p] + k0);
            cp16(st +  8192 + dsts[p], Alo + gA[p] + k0);
            cp16(st + 16384 + dsts[p], Bhi + gB[p] + k0);
            cp16(st + 24576 + dsts[p], Blo + gB[p] + k0);
        }
        CP_COMMIT();
    }

    for (int c = 0; c < NCHUNK; c++) {
        if (c + 2 < NCHUNK) {
            int ch = c + 2;
            uint32_t st = sbase + (ch % 3) * STG;
            int k0 = ch * 32;
#pragma unroll
            for (int p = 0; p < 2; p++) {
                cp16(st +     0 + dsts[p], Ahi + gA[p] + k0);
                cp16(st +  8192 + dsts[p], Alo + gA[p] + k0);
                cp16(st + 16384 + dsts[p], Bhi + gB[p] + k0);
                cp16(st + 24576 + dsts[p], Blo + gB[p] + k0);
            }
            CP_COMMIT();
            CP_WAIT(2);
        } else if (c + 1 < NCHUNK) {
            CP_WAIT(1);
        } else {
            CP_WAIT(0);
        }
        __syncthreads();

        uint32_t st = sbase + (c % 3) * STG;
        uint32_t aHiB = st, aLoB = st + 8192, bHiB = st + 16384, bLoB = st + 24576;

#pragma unroll
        for (int ks = 0; ks < 2; ks++) {
            uint32_t ah[4][4], al[4][4], bh[2][4], bl[2][4];
#pragma unroll
            for (int mt = 0; mt < 4; mt++)
                LDSM4(ah[mt], aHiB + adr32(wm * 64 + mt * 16 + arow, 2 * ks + acb));
#pragma unroll
            for (int np = 0; np < 2; np++)
                LDSM4(bh[np], bHiB + adr32(wn * 32 + np * 16 + brow, 2 * ks + bcb));
#pragma unroll
            for (int mt = 0; mt < 4; mt++)
#pragma unroll
                for (int nt = 0; nt < 4; nt++)
                    MMA16816(acc[mt][nt], ah[mt], bh[nt >> 1][(nt & 1) * 2],
                             bh[nt >> 1][(nt & 1) * 2 + 1]);
#pragma unroll
            for (int np = 0; np < 2; np++)
                LDSM4(bl[np], bLoB + adr32(wn * 32 + np * 16 + brow, 2 * ks + bcb));
#pragma unroll
            for (int mt = 0; mt < 4; mt++)
#pragma unroll
                for (int nt = 0; nt < 4; nt++)
                    MMA16816(acc[mt][nt], ah[mt], bl[nt >> 1][(nt & 1) * 2],
                             bl[nt >> 1][(nt & 1) * 2 + 1]);
#pragma unroll
            for (int mt = 0; mt < 4; mt++)
                LDSM4(al[mt], aLoB + adr32(wm * 64 + mt * 16 + arow, 2 * ks + acb));
#pragma unroll
            for (int mt = 0; mt < 4; mt++)
#pragma unroll
                for (int nt = 0; nt < 4; nt++)
                    MMA16816(acc[mt][nt], al[mt], bh[nt >> 1][(nt & 1) * 2],
                             bh[nt >> 1][(nt & 1) * 2 + 1]);
        }
        __syncthreads();
    }

    // epilogue with output routing
    float* C; const float* bias; int NN, c0;
    if (n0 < 2048)      { C = C0; bias = b0; NN = 2048; c0 = n0; }
    else if (n0 < 2560) { C = C1; bias = b1; NN = 512;  c0 = n0 - 2048; }
    else                { C = C2; bias = b2; NN = 512;  c0 = n0 - 2560; }

#pragma unroll
    for (int mt = 0; mt < 4; mt++) {
        int r0 = m0 + wm * 64 + mt * 16 + (lane >> 2);
#pragma unroll
        for (int nt = 0; nt < 4; nt++) {
            int cc = c0 + wn * 32 + nt * 8 + (lane & 3) * 2;
            float bb0 = bias[cc], bb1 = bias[cc + 1];
            float2 v0 = make_float2(acc[mt][nt][0] + bb0, acc[mt][nt][1] + bb1);
            float2 v1 = make_float2(acc[mt][nt][2] + bb0, acc[mt][nt][3] + bb1);
            *(float2*)(C + (size_t)r0 * NN + cc) = v0;
            *(float2*)(C + (size_t)(r0 + 8) * NN + cc) = v1;
        }
    }
}

// ---------------------------------------------------------------------------
// RoPE + pack to [b,h,t,d] bf16 hi/lo; optional pre-scale (softmax scale on Q)
// ---------------------------------------------------------------------------
__global__ void rope_pack(const float* __restrict__ X,
                          __nv_bfloat16* __restrict__ hi,
                          __nv_bfloat16* __restrict__ lo, int nh, float sc)
{
    int idx = blockIdx.x * blockDim.x + threadIdx.x;
    int total = MROWS * nh * 64;
    if (idx >= total) return;
    int d = idx & 63;
    int h = (idx >> 6) % nh;
    int r = idx / (64 * nh);
    int t = r & (TSEQ - 1);
    int b = r >> 11;

    const float* p = X + (size_t)r * (nh * DHEAD) + h * DHEAD + d;
    float x1 = p[0], x2 = p[64];
    float inv = powf(10000.f, -(float)d * (1.f / 64.f));
    float s, c;
    sincosf((float)t * inv, &s, &c);
    float y1 = (x1 * c - x2 * s) * sc;
    float y2 = (x1 * s + x2 * c) * sc;

    size_t orow = ((size_t)(b * nh + h) * TSEQ + t) * DHEAD;
    __nv_bfloat16 h1 = __float2bfloat16_rn(y1);
    __nv_bfloat16 h2 = __float2bfloat16_rn(y2);
    hi[orow + d]      = h1;
    lo[orow + d]      = __float2bfloat16_rn(y1 - __bfloat162float(h1));
    hi[orow + 64 + d] = h2;
    lo[orow + 64 + d] = __float2bfloat16_rn(y2 - __bfloat162float(h2));
}

// ---------------------------------------------------------------------------
// V pack: [b,t,g,d] fp32 -> [b,g,t,d] bf16 hi/lo
// ---------------------------------------------------------------------------
__global__ void pack_v(const float* __restrict__ V,
                       __nv_bfloat16* __restrict__ hi,
                       __nv_bfloat16* __restrict__ lo)
{
    int idx = blockIdx.x * blockDim.x + threadIdx.x;
    if (idx >= MROWS * KVC / 4) return;
    int d4 = idx & 31;
    int g = (idx >> 5) & 3;
    int r = idx >> 7;
    int t = r & (TSEQ - 1);
    int b = r >> 11;

    float4 v = *(const float4*)(V + (size_t)r * KVC + g * DHEAD + d4 * 4);
    size_t o = ((size_t)(b * NGROUP + g) * TSEQ + t) * DHEAD + d4 * 4;
    __nv_bfloat16 h0 = __float2bfloat16_rn(v.x);
    __nv_bfloat16 h1 = __float2bfloat16_rn(v.y);
    __nv_bfloat16 h2 = __float2bfloat16_rn(v.z);
    __nv_bfloat16 h3 = __float2bfloat16_rn(v.w);
    *(__nv_bfloat162*)(hi + o)     = __nv_bfloat162(h0, h1);
    *(__nv_bfloat162*)(hi + o + 2) = __nv_bfloat162(h2, h3);
    *(__nv_bfloat162*)(lo + o)     = __nv_bfloat162(
        __float2bfloat16_rn(v.x - __bfloat162float(h0)),
        __float2bfloat16_rn(v.y - __bfloat162float(h1)));
    *(__nv_bfloat162*)(lo + o + 2) = __nv_bfloat162(
        __float2bfloat16_rn(v.z - __bfloat162float(h2)),
        __float2bfloat16_rn(v.w - __bfloat162float(h3)));
}

// ---------------------------------------------------------------------------
// HMMA flash attention. grid (32 qtiles, 32 bh), 128 threads (4 warps x 16 q).
// KV tile 32, double-buffered; Q frags hoisted into registers.
// Q pre-scaled by 1/sqrt(d) at pack time.
// ---------------------------------------------------------------------------
__global__ __launch_bounds__(128, 2) void attn_mma(
    const __nv_bfloat16* __restrict__ qhi, const __nv_bfloat16* __restrict__ qlo,
    const __nv_bfloat16* __restrict__ khi, const __nv_bfloat16* __restrict__ klo,
    const __nv_bfloat16* __restrict__ vhi, const __nv_bfloat16* __restrict__ vlo,
    __nv_bfloat16* __restrict__ ohi, __nv_bfloat16* __restrict__ olo)
{
    extern __shared__ char sm[];
    uint32_t sb = (cvta_s(sm) + 1023) & ~1023u;
    const uint32_t sQh = sb, sQl = sb + 16384;
    const uint32_t sKV = sb + 32768;   // stage: +s*32768; Kh 0 Kl 8192 Vh 16384 Vl 24576

    const int tid = threadIdx.x, w = tid >> 5, lane = tid & 31;
    const int b = blockIdx.y >> 4, h = blockIdx.y & 15, g = h >> 2;
    const int qs = blockIdx.x * 64;

    // Q tile load (64 rows x 128 dims, hi + lo)
    {
        size_t qb = ((size_t)(b * NHEAD + h) * TSEQ + qs) * DHEAD;
#pragma unroll
        for (int p = 0; p < 8; p++) {
            int idx = tid + p * 128;
            int row = idx >> 4, ch = idx & 15;
            uint32_t d = adr128(row, ch);
            size_t s = qb + (size_t)row * DHEAD + ch * 8;
            cp16(sQh + d, qhi + s);
            cp16(sQl + d, qlo + s);
        }
    }
    CP_COMMIT();

    int t0 = qs - SWIN; if (t0 < 0) t0 = 0;
    const int sink = (t0 > 0) ? 1 : 0;
    const int ntiles = sink + (qs + 64 - t0) / 32;
    const size_t kvbase = (size_t)(b * NGROUP + g) * TSEQ * DHEAD;

    // load KV tile 0
    {
        int ts = sink ? 0 : t0;
        size_t kb = kvbase + (size_t)ts * DHEAD;
#pragma unroll
        for (int p = 0; p < 4; p++) {
            int idx = tid + p * 128;
            int row = idx >> 4, ch = idx & 15;
            uint32_t d = adr128(row, ch);
            size_t s = kb + (size_t)row * DHEAD + ch * 8;
            cp16(sKV +     0 + d, khi + s);
            cp16(sKV +  8192 + d, klo + s);
            cp16(sKV + 16384 + d, vhi + s);
            cp16(sKV + 24576 + d, vlo + s);
        }
    }
    CP_COMMIT();

    const int arow = (lane & 7) + ((lane >> 3) & 1) * 8;
    const int acb  = lane >> 4;
    const int brow = (lane & 7) + (lane >> 4) * 8;
    const int bcb  = (lane >> 3) & 1;
    const int vr_i = ((lane >> 3) & 1) * 8 + (lane & 7);
    const int vc_i = lane >> 4;
    const int i0 = qs + w * 16 + (lane >> 2);
    const int i1 = i0 + 8;
    const int iwmax = qs + w * 16 + 15;
    const int cbs = (lane & 3) * 2;

    // wait for Q (leaves at most KV0 pending), hoist Q fragments
    CP_WAIT(1);
    __syncthreads();
    uint32_t qh[8][4], ql[8][4];
#pragma unroll
    for (int kc = 0; kc < 8; kc++) {
        uint32_t off = adr128(w * 16 + arow, 2 * kc + acb);
        LDSM4(qh[kc], sQh + off);
        LDSM4(ql[kc], sQl + off);
    }

    float o[16][4];
#pragma unroll
    for (int i = 0; i < 16; i++) { o[i][0] = 0.f; o[i][1] = 0.f; o[i][2] = 0.f; o[i][3] = 0.f; }
    float m0 = -1e30f, m1 = -1e30f, l0 = 0.f, l1 = 0.f;

    for (int it = 0; it < ntiles; it++) {
        const bool snk = (sink && it == 0);
        const int ts = snk ? 0 : t0 + (it - sink) * 32;
        const int n2max = snk ? 1 : 2;

        if (it + 1 < ntiles) {
            int tsn = (sink && it + 1 == 0) ? 0 : t0 + (it + 1 - sink) * 32;
            uint32_t st = sKV + ((it + 1) & 1) * 32768;
            size_t kb = kvbase + (size_t)tsn * DHEAD;
#pragma unroll
            for (int p = 0; p < 4; p++) {
                int idx = tid + p * 128;
                int row = idx >> 4, ch = idx & 15;
                uint32_t d = adr128(row, ch);
                size_t s = kb + (size_t)row * DHEAD + ch * 8;
                cp16(st +     0 + d, khi + s);
                cp16(st +  8192 + d, klo + s);
                cp16(st + 16384 + d, vhi + s);
                cp16(st + 24576 + d, vlo + s);
            }
            CP_COMMIT();
            CP_WAIT(1);
        } else {
            CP_WAIT(0);
        }
        __syncthreads();

        uint32_t stg = sKV + (it & 1) * 32768;
        uint32_t sKh = stg, sKl = stg + 8192, sVh = stg + 16384, sVl = stg + 24576;

        // S = Q @ K^T (3-term)
        float sc[4][4];
#pragma unroll
        for (int i = 0; i < 4; i++) { sc[i][0] = 0.f; sc[i][1] = 0.f; sc[i][2] = 0.f; sc[i][3] = 0.f; }

        for (int n2 = 0; n2 < n2max; n2++) {
            if (ts + n2 * 16 > iwmax) break;   // fully masked for this warp
#pragma unroll
            for (int kc = 0; kc < 8; kc++) {
                uint32_t off = adr128(n2 * 16 + brow, 2 * kc + bcb);
                uint32_t kh_[4], kl_[4];
                LDSM4(kh_, sKh + off);
                LDSM4(kl_, sKl + off);
                MMA16816(sc[2 * n2],     qh[kc], kh_[0], kh_[1]);
                MMA16816(sc[2 * n2],     qh[kc], kl_[0], kl_[1]);
                MMA16816(sc[2 * n2],     ql[kc], kh_[0], kh_[1]);
                MMA16816(sc[2 * n2 + 1], qh[kc], kh_[2], kh_[3]);
                MMA16816(sc[2 * n2 + 1], qh[kc], kl_[2], kl_[3]);
                MMA16816(sc[2 * n2 + 1], ql[kc], kh_[2], kh_[3]);
            }
        }

        // mask + row max (scale already folded into Q)
        float rm0 = -1e30f, rm1 = -1e30f;
#pragma unroll
        for (int nt = 0; nt < 4; nt++) {
            int j0 = ts + nt * 8 + cbs, j1 = j0 + 1;
            sc[nt][0] = (j0 <= i0 && (j0 >= i0 - SWIN || j0 < SINK)) ? sc[nt][0] : -1e30f;
            sc[nt][1] = (j1 <= i0 && (j1 >= i0 - SWIN || j1 < SINK)) ? sc[nt][1] : -1e30f;
            sc[nt][2] = (j0 <= i1 && (j0 >= i1 - SWIN || j0 < SINK)) ? sc[nt][2] : -1e30f;
            sc[nt][3] = (j1 <= i1 && (j1 >= i1 - SWIN || j1 < SINK)) ? sc[nt][3] : -1e30f;
            rm0 = fmaxf(rm0, fmaxf(sc[nt][0], sc[nt][1]));
            rm1 = fmaxf(rm1, fmaxf(sc[nt][2], sc[nt][3]));
        }
        rm0 = fmaxf(rm0, __shfl_xor_sync(0xffffffffu, rm0, 1));
        rm0 = fmaxf(rm0, __shfl_xor_sync(0xffffffffu, rm0, 2));
        rm1 = fmaxf(rm1, __shfl_xor_sync(0xffffffffu, rm1, 1));
        rm1 = fmaxf(rm1, __shfl_xor_sync(0xffffffffu, rm1, 2));
        float mn0 = fmaxf(m0, rm0), mn1 = fmaxf(m1, rm1);
        float c0 = __expf(m0 - mn0), c1 = __expf(m1 - mn1);
        m0 = mn0; m1 = mn1;

#pragma unroll
        for (int nd = 0; nd < 16; nd++) {
            o[nd][0] *= c0; o[nd][1] *= c0; o[nd][2] *= c1; o[nd][3] *= c1;
        }

        float rs0 = 0.f, rs1 = 0.f;
        for (int k2 = 0; k2 < n2max; k2++) {
            if (ts + k2 * 16 > iwmax) break;
            uint32_t aP[4], aPl[4];
#pragma unroll
            for (int q2 = 0; q2 < 2; q2++) {
                int nt = 2 * k2 + q2;
                float p00 = __expf(sc[nt][0] - mn0), p01 = __expf(sc[nt][1] - mn0);
                float p10 = __expf(sc[nt][2] - mn1), p11 = __expf(sc[nt][3] - mn1);
                rs0 += p00 + p01; rs1 += p10 + p11;
                __nv_bfloat162 h0v = __floats2bfloat162_rn(p00, p01);
                __nv_bfloat162 h1v = __floats2bfloat162_rn(p10, p11);
                __nv_bfloat162 l0v = __floats2bfloat162_rn(
                    p00 - __bfloat162float(h0v.x), p01 - __bfloat162float(h0v.y));
                __nv_bfloat162 l1v = __floats2bfloat162_rn(
                    p10 - __bfloat162float(h1v.x), p11 - __bfloat162float(h1v.y));
                aP[2 * q2]      = *(uint32_t*)&h0v;
                aP[2 * q2 + 1]  = *(uint32_t*)&h1v;
                aPl[2 * q2]     = *(uint32_t*)&l0v;
                aPl[2 * q2 + 1] = *(uint32_t*)&l1v;
            }
#pragma unroll
            for (int ndp = 0; ndp < 8; ndp++) {
                uint32_t voff = adr128(k2 * 16 + vr_i, ndp * 2 + vc_i);
                uint32_t bv[4], bvl[4];
                LDSM4T(bv,  sVh + voff);
                LDSM4T(bvl, sVl + voff);
                MMA16816(o[ndp * 2],     aP,  bv[0],  bv[1]);
                MMA16816(o[ndp * 2],     aP,  bvl[0], bvl[1]);
                MMA16816(o[ndp * 2],     aPl, bv[0],  bv[1]);
                MMA16816(o[ndp * 2 + 1], aP,  bv[2],  bv[3]);
                MMA16816(o[ndp * 2 + 1], aP,  bvl[2], bvl[3]);
                MMA16816(o[ndp * 2 + 1], aPl, bv[2],  bv[3]);
            }
        }
        rs0 += __shfl_xor_sync(0xffffffffu, rs0, 1);
        rs0 += __shfl_xor_sync(0xffffffffu, rs0, 2);
        rs1 += __shfl_xor_sync(0xffffffffu, rs1, 1);
        rs1 += __shfl_xor_sync(0xffffffffu, rs1, 2);
        l0 = l0 * c0 + rs0;
        l1 = l1 * c1 + rs1;

        __syncthreads();   // compute done before next prefetch reuses buffer
    }

    // epilogue: O/l -> bf16 hi/lo, layout [b*T+t, h*128+d]
    float il0 = 1.f / l0, il1 = 1.f / l1;
    size_t or0 = (size_t)(b * TSEQ + qs + w * 16 + (lane >> 2)) * CEMB + h * DHEAD;
    size_t or1 = or0 + (size_t)8 * CEMB;
#pragma unroll
    for (int nd = 0; nd < 16; nd++) {
        int col = nd * 8 + cbs;
        float v0 = o[nd][0] * il0, v1 = o[nd][1] * il0;
        float v2 = o[nd][2] * il1, v3 = o[nd][3] * il1;
        __nv_bfloat162 h0v = __floats2bfloat162_rn(v0, v1);
        __nv_bfloat162 h1v = __floats2bfloat162_rn(v2, v3);
        __nv_bfloat162 l0v = __floats2bfloat162_rn(
            v0 - __bfloat162float(h0v.x), v1 - __bfloat162float(h0v.y));
        __nv_bfloat162 l1v = __floats2bfloat162_rn(
            v2 - __bfloat162float(h1v.x), v3 - __bfloat162float(h1v.y));
        *(__nv_bfloat162*)(ohi + or0 + col) = h0v;
        *(__nv_bfloat162*)(olo + or0 + col) = l0v;
        *(__nv_bfloat162*)(ohi + or1 + col) = h1v;
        *(__nv_bfloat162*)(olo + or1 + col) = l1v;
    }
}

// ---------------------------------------------------------------------------
extern "C" void kernel_launch(void* const* d_in, const int* in_sizes, int n_in,
                              void* d_out, int out_size)
{
    const float* x  = (const float*)d_in[0];
    const float* Wq = (const float*)d_in[1];
    const float* bq = (const float*)d_in[2];
    const float* Wk = (const float*)d_in[3];
    const float* bk = (const float*)d_in[4];
    const float* Wv = (const float*)d_in[5];
    const float* bv = (const float*)d_in[6];
    const float* Wo = (const float*)d_in[7];
    const float* bo = (const float*)d_in[8];
    float* out = (float*)d_out;

    float *Q, *K, *V;
    cudaGetSymbolAddress((void**)&Q, g_Q);
    cudaGetSymbolAddress((void**)&K, g_K);
    cudaGetSymbolAddress((void**)&V, g_V);
    __nv_bfloat16 *xhi, *xlo, *ohi, *olo, *qhi, *qlo, *khi, *klo, *vhi, *vlo;
    __nv_bfloat16 *wth, *wtl, *woh, *wol;
    cudaGetSymbolAddress((void**)&xhi, g_xhi);
    cudaGetSymbolAddress((void**)&xlo, g_xlo);
    cudaGetSymbolAddress((void**)&ohi, g_ohi);
    cudaGetSymbolAddress((void**)&olo, g_olo);
    cudaGetSymbolAddress((void**)&qhi, g_qhi);
    cudaGetSymbolAddress((void**)&qlo, g_qlo);
    cudaGetSymbolAddress((void**)&khi, g_khi);
    cudaGetSymbolAddress((void**)&klo, g_klo);
    cudaGetSymbolAddress((void**)&vhi, g_vhi);
    cudaGetSymbolAddress((void**)&vlo, g_vlo);
    cudaGetSymbolAddress((void**)&wth, g_WT_hi);
    cudaGetSymbolAddress((void**)&wtl, g_WT_lo);
    cudaGetSymbolAddress((void**)&woh, g_WoT_hi);
    cudaGetSymbolAddress((void**)&wol, g_WoT_lo);

    const int GEMM_SMEM = 99328;   // 3 * 32KB + align
    cudaFuncSetAttribute(gemm_mma, cudaFuncAttributeMaxDynamicSharedMemorySize, GEMM_SMEM);
    const int ATTN_SMEM = 99328;   // 32KB Q + 2 * 32KB KV + align
    cudaFuncSetAttribute(attn_mma, cudaFuncAttributeMaxDynamicSharedMemorySize, ATTN_SMEM);

    // input split / packed weight transposes
    {
        int n4 = (MROWS * CEMB) / 4;
        split_f32<<<(n4 + 255) / 256, 256>>>(x, xhi, xlo, n4);
    }
    tsplit<<<dim3(CEMB / 32, CEMB / 32), dim3(32, 8)>>>(Wq, wth, wtl, CEMB, CEMB);
    tsplit<<<dim3(KVC / 32, CEMB / 32), dim3(32, 8)>>>(
        Wk, wth + (size_t)2048 * CEMB, wtl + (size_t)2048 * CEMB, CEMB, KVC);
    tsplit<<<dim3(KVC / 32, CEMB / 32), dim3(32, 8)>>>(
        Wv, wth + (size_t)2560 * CEMB, wtl + (size_t)2560 * CEMB, CEMB, KVC);
    tsplit<<<dim3(CEMB / 32, CEMB / 32), dim3(32, 8)>>>(Wo, woh, wol, CEMB, CEMB);

    // fused QKV projection (one launch, 768 CTAs)
    gemm_mma<<<dim3(NQKV / 128, MROWS / 128), 256, GEMM_SMEM>>>(
        xhi, xlo, wth, wtl, Q, bq, K, bk, V, bv);

    // RoPE + pack (softmax scale folded into Q)
    rope_pack<<<(MROWS * NHEAD * 64) / 256, 256>>>(Q, qhi, qlo, NHEAD, 0.08838834764831845f);
    rope_pack<<<(MROWS * NGROUP * 64) / 256, 256>>>(K, khi, klo, NGROUP, 1.0f);
    pack_v<<<(MROWS * KVC / 4 + 255) / 256, 256>>>(V, vhi, vlo);

    // flash attention
    attn_mma<<<dim3(TSEQ / 64, 2 * NHEAD), 128, ATTN_SMEM>>>(
        qhi, qlo, khi, klo, vhi, vlo, ohi, olo);

    // output projection
    gemm_mma<<<dim3(CEMB / 128, MROWS / 128), 256, GEMM_SMEM>>>(
        ohi, olo, woh, wol, out, bo, out, bo, out, bo);
}